// round 11
// baseline (speedup 1.0000x reference)
#include <cuda_runtime.h>
#include <cuda_bf16.h>
#include <math.h>
#include <stdint.h>

#define T_STEPS 512
#define BATCH   64
#define IN_DIM  1024
#define HID     1024
#define GATES   4096   // 4*HID, gate order i,g,f,o
#define NCTA    128

// ---------------- device scratch ----------------
__device__ float g_wx[(size_t)T_STEPS * BATCH * GATES];   // 512 MB
__device__ unsigned g_arrive[NCTA * 8];                   // 32B-strided per-CTA step flags
__device__ unsigned g_bar;                                // end-of-launch cleanup

__device__ __nv_bfloat16 g_xhi[(size_t)T_STEPS * BATCH * IN_DIM];
__device__ __nv_bfloat16 g_xlo[(size_t)T_STEPS * BATCH * IN_DIM];
__device__ __nv_bfloat16 g_Wthi[(size_t)GATES * IN_DIM];   // transposed [N][K]
__device__ __nv_bfloat16 g_Wtlo[(size_t)GATES * IN_DIM];
__device__ __nv_bfloat16 g_Rthi[(size_t)GATES * HID];      // transposed [N][K]
__device__ __nv_bfloat16 g_Rtlo[(size_t)GATES * HID];
__device__ __nv_bfloat16 g_hhi[2][BATCH * HID];            // ping-pong h bf16 hi/lo
__device__ __nv_bfloat16 g_hlo[2][BATCH * HID];

// ---------------- helpers ----------------
__device__ __forceinline__ void mma16816(float* c, const uint32_t* a, const uint32_t* b)
{
    asm volatile(
        "mma.sync.aligned.m16n8k16.row.col.f32.bf16.bf16.f32 "
        "{%0,%1,%2,%3}, {%4,%5,%6,%7}, {%8,%9}, {%0,%1,%2,%3};"
        : "+f"(c[0]), "+f"(c[1]), "+f"(c[2]), "+f"(c[3])
        : "r"(a[0]), "r"(a[1]), "r"(a[2]), "r"(a[3]), "r"(b[0]), "r"(b[1]));
}

__device__ __forceinline__ void split_bf16(float v, __nv_bfloat16& hi, __nv_bfloat16& lo)
{
    hi = __float2bfloat16_rn(v);
    lo = __float2bfloat16_rn(v - __bfloat162float(hi));
}

__device__ __forceinline__ float tanh_fast(float x)
{
    float y;
    asm("tanh.approx.f32 %0, %1;" : "=f"(y) : "f"(x));
    return y;
}
__device__ __forceinline__ float sigmoid_fast(float x)
{
    return 0.5f * tanh_fast(0.5f * x) + 0.5f;
}

__device__ __forceinline__ float2 ldcg_f2(const float* p)
{
    float2 v;
    asm volatile("ld.global.cg.v2.f32 {%0,%1}, [%2];" : "=f"(v.x), "=f"(v.y) : "l"(p));
    return v;
}
__device__ __forceinline__ unsigned ldcg_u32(const unsigned* p)
{
    unsigned v;
    asm volatile("ld.global.cg.u32 %0, [%1];" : "=r"(v) : "l"(p));
    return v;
}

// ---------------- conversion kernels ----------------
__global__ void convert_x(const float* __restrict__ x)
{
    size_t i = (size_t)blockIdx.x * blockDim.x + threadIdx.x;
    if (i < (size_t)T_STEPS * BATCH * IN_DIM) {
        __nv_bfloat16 hi, lo;
        split_bf16(x[i], hi, lo);
        g_xhi[i] = hi;
        g_xlo[i] = lo;
    }
}

__global__ void convert_W(const float* __restrict__ src)
{
    __shared__ float tile[32][33];
    int n0 = blockIdx.x * 32, k0 = blockIdx.y * 32;
    int tx = threadIdx.x, ty = threadIdx.y;
#pragma unroll
    for (int i = 0; i < 32; i += 8)
        tile[ty + i][tx] = src[(size_t)(k0 + ty + i) * GATES + n0 + tx];
    __syncthreads();
#pragma unroll
    for (int i = 0; i < 32; i += 8) {
        float v = tile[tx][ty + i];
        size_t o = (size_t)(n0 + ty + i) * IN_DIM + k0 + tx;
        __nv_bfloat16 hi, lo;
        split_bf16(v, hi, lo);
        g_Wthi[o] = hi;
        g_Wtlo[o] = lo;
    }
}

__global__ void convert_R(const float* __restrict__ src)
{
    __shared__ float tile[32][33];
    int n0 = blockIdx.x * 32, k0 = blockIdx.y * 32;
    int tx = threadIdx.x, ty = threadIdx.y;
#pragma unroll
    for (int i = 0; i < 32; i += 8)
        tile[ty + i][tx] = src[(size_t)(k0 + ty + i) * GATES + n0 + tx];
    __syncthreads();
#pragma unroll
    for (int i = 0; i < 32; i += 8) {
        float v = tile[tx][ty + i];
        size_t o = (size_t)(n0 + ty + i) * HID + k0 + tx;
        __nv_bfloat16 hi, lo;
        split_bf16(v, hi, lo);
        g_Rthi[o] = hi;
        g_Rtlo[o] = lo;
    }
}

// ---------------- wx GEMM: cp.async double-buffered ----------------
#define WXS 40
#define WXC (128 * WXS)                 // elems per array per buffer
#define WX_SMEM (2 * 4 * WXC * 2)       // 81920 B

__device__ __forceinline__ void wx_stage(uint32_t smb, size_t m0, int n0,
                                         int k0, int b, int tid)
{
    const __nv_bfloat16* srcs[4];
    srcs[0] = g_xhi;  srcs[1] = g_xlo;  srcs[2] = g_Wthi;  srcs[3] = g_Wtlo;
#pragma unroll
    for (int arr = 0; arr < 4; arr++) {
        size_t base = (arr < 2) ? m0 : (size_t)n0;
#pragma unroll
        for (int rep = 0; rep < 2; rep++) {
            int id = tid + rep * 256;
            int row = id >> 2, seg = id & 3;
            const __nv_bfloat16* src = srcs[arr]
                + (base + row) * IN_DIM + k0 + seg * 8;
            uint32_t dst = smb + (uint32_t)(((b * 4 + arr) * WXC
                                             + row * WXS + seg * 8) * 2);
            asm volatile("cp.async.cg.shared.global [%0], [%1], 16;"
                         :: "r"(dst), "l"(src));
        }
    }
    asm volatile("cp.async.commit_group;");
}

__global__ __launch_bounds__(256) void wx_mma(const float* __restrict__ bias)
{
    extern __shared__ __align__(16) unsigned char wxsm[];
    __nv_bfloat16* S = (__nv_bfloat16*)wxsm;
    uint32_t smb = (uint32_t)__cvta_generic_to_shared(S);

    int tid  = threadIdx.x;
    int lane = tid & 31, w = tid >> 5;
    int g = lane >> 2, tq = lane & 3;
    size_t m0 = (size_t)blockIdx.y * 128;
    int n0 = blockIdx.x * 128;
    int wm = w & 1, wn = w >> 1;

    float acc[4][4][4];
#pragma unroll
    for (int mt = 0; mt < 4; mt++)
#pragma unroll
        for (int nt = 0; nt < 4; nt++)
#pragma unroll
            for (int r = 0; r < 4; r++) acc[mt][nt][r] = 0.f;

    wx_stage(smb, m0, n0, 0, 0, tid);

    for (int kc = 0; kc < 32; kc++) {
        int cur = kc & 1;
        if (kc < 31) {
            wx_stage(smb, m0, n0, (kc + 1) * 32, cur ^ 1, tid);
            asm volatile("cp.async.wait_group 1;");
        } else {
            asm volatile("cp.async.wait_group 0;");
        }
        __syncthreads();

        const __nv_bfloat16* Ah = S + (cur * 4 + 0) * WXC;
        const __nv_bfloat16* Al = S + (cur * 4 + 1) * WXC;
        const __nv_bfloat16* Bh = S + (cur * 4 + 2) * WXC;
        const __nv_bfloat16* Bl = S + (cur * 4 + 3) * WXC;

#pragma unroll
        for (int ks = 0; ks < 2; ks++) {
            int ko = ks * 16;
            uint32_t bh[4][2], bl[4][2];
#pragma unroll
            for (int nt = 0; nt < 4; nt++) {
                int r = wn * 32 + nt * 8 + g;
                bh[nt][0] = *(const uint32_t*)&Bh[r * WXS + ko + 2 * tq];
                bh[nt][1] = *(const uint32_t*)&Bh[r * WXS + ko + 2 * tq + 8];
                bl[nt][0] = *(const uint32_t*)&Bl[r * WXS + ko + 2 * tq];
                bl[nt][1] = *(const uint32_t*)&Bl[r * WXS + ko + 2 * tq + 8];
            }
#pragma unroll
            for (int mt = 0; mt < 4; mt++) {
                int r0 = wm * 64 + mt * 16 + g, r1 = r0 + 8;
                uint32_t ah[4], al[4];
                ah[0] = *(const uint32_t*)&Ah[r0 * WXS + ko + 2 * tq];
                ah[1] = *(const uint32_t*)&Ah[r1 * WXS + ko + 2 * tq];
                ah[2] = *(const uint32_t*)&Ah[r0 * WXS + ko + 2 * tq + 8];
                ah[3] = *(const uint32_t*)&Ah[r1 * WXS + ko + 2 * tq + 8];
                al[0] = *(const uint32_t*)&Al[r0 * WXS + ko + 2 * tq];
                al[1] = *(const uint32_t*)&Al[r1 * WXS + ko + 2 * tq];
                al[2] = *(const uint32_t*)&Al[r0 * WXS + ko + 2 * tq + 8];
                al[3] = *(const uint32_t*)&Al[r1 * WXS + ko + 2 * tq + 8];
#pragma unroll
                for (int nt = 0; nt < 4; nt++) mma16816(acc[mt][nt], ah, bh[nt]);
#pragma unroll
                for (int nt = 0; nt < 4; nt++) mma16816(acc[mt][nt], ah, bl[nt]);
#pragma unroll
                for (int nt = 0; nt < 4; nt++) mma16816(acc[mt][nt], al, bh[nt]);
            }
        }
        __syncthreads();
    }

#pragma unroll
    for (int mt = 0; mt < 4; mt++) {
        size_t row = m0 + wm * 64 + mt * 16 + g;
#pragma unroll
        for (int nt = 0; nt < 4; nt++) {
            int col = n0 + wn * 32 + nt * 8 + 2 * tq;
            g_wx[row * GATES + col]           = acc[mt][nt][0] + bias[col];
            g_wx[row * GATES + col + 1]       = acc[mt][nt][1] + bias[col + 1];
            g_wx[(row + 8) * GATES + col]     = acc[mt][nt][2] + bias[col];
            g_wx[(row + 8) * GATES + col + 1] = acc[mt][nt][3] + bias[col + 1];
        }
    }
}

// ---------------- persistent LSTM recurrence v5 ----------------
// Per-chunk producer flags (no global barrier). Chunk kc of group grp covers
// h cols [grp*512 + kc*64, +64), produced by CTAs [grp*64 + kc*8, +8).
// CRITICAL: every spin loop sleeps via __nanosleep — a tight spin coexisting
// with compute warps on the same SMSP starves them under hi-wid-first
// arbitration (R10 livelock). Sleeping warps are ineligible -> compute issues.
#define RSTR 1032
#define HSTR 72
#define HBUF_B (16 * HSTR * 2)
#define H_REGION (32 * HBUF_B)
#define RED_OFF (2 * 32 * RSTR * 2 + H_REGION)
#define SMEM_PERS (RED_OFF + 2 * 128 * 9 * 4)

__device__ __forceinline__ void wait_flags(int grp, int kc, int t, int lane)
{
    const unsigned* f = &g_arrive[(grp * 64 + kc * 8 + (lane & 7)) * 8];
    while (!__all_sync(0xffffffffu, (int)(ldcg_u32(f) >= (unsigned)t)))
        __nanosleep(40);                         // starvation-free backoff
    asm volatile("membar.gl;");
}

__device__ __forceinline__ void stage_warp(uint32_t hbase_sm,
                                           const __nv_bfloat16* hhi,
                                           const __nv_bfloat16* hlo,
                                           int w, int grp, int wm,
                                           int kc, int b, int lane)
{
#pragma unroll
    for (int s = 0; s < 8; s++) {
        int isLo = s >> 2;
        int id = (s & 3) * 32 + lane;
        int row = id >> 3, segk = id & 7;
        const __nv_bfloat16* src = (isLo ? hlo : hhi)
            + (size_t)(wm * 16 + row) * HID + grp * 512 + kc * 64 + segk * 8;
        uint32_t dst = hbase_sm
            + (uint32_t)(((w * 2 + b) * 2 + isLo) * HBUF_B + row * (HSTR * 2) + segk * 16);
        asm volatile("cp.async.cg.shared.global [%0], [%1], 16;" :: "r"(dst), "l"(src));
    }
    asm volatile("cp.async.commit_group;");
}

__global__ __launch_bounds__(256) void lstm_persistent(float* __restrict__ out_base)
{
    extern __shared__ __align__(16) unsigned char smem_raw[];
    __nv_bfloat16* Rh = (__nv_bfloat16*)smem_raw;
    __nv_bfloat16* Rl = Rh + 32 * RSTR;
    __nv_bfloat16* Hbase = Rl + 32 * RSTR;
    float* Red = (float*)(smem_raw + RED_OFF);
    uint32_t hbase_sm = (uint32_t)__cvta_generic_to_shared(Hbase);

    const int tid  = threadIdx.x;
    const int lane = tid & 31, w = tid >> 5;
    const int g = lane >> 2, tq = lane & 3;
    const int grp = w >> 2, wm = w & 3;
    const int hc0 = blockIdx.x * 8;

    for (int rep = 0; rep < 16; rep++) {
        int id = rep * 256 + tid;
        int row = id >> 7, seg = id & 127;
        size_t src = (size_t)((row >> 3) * HID + hc0 + (row & 7)) * HID + seg * 8;
        *(uint4*)&Rh[row * RSTR + seg * 8] = *(const uint4*)&g_Rthi[src];
        *(uint4*)&Rl[row * RSTR + seg * 8] = *(const uint4*)&g_Rtlo[src];
    }
    __syncthreads();

    float c_reg[2] = {0.f, 0.f};

    for (int t = 0; t < T_STEPS; t++) {
        // prefetch this group's wx half (DRAM, independent of h)
        float2 wxp[4];
        {
            const float* wx_t = g_wx + (size_t)t * BATCH * GATES;
            int brow = wm * 16 + g + grp * 8;
#pragma unroll
            for (int gate = 0; gate < 4; gate++)
                wxp[gate] = ldcg_f2(wx_t + (size_t)brow * GATES + gate * HID + hc0 + 2 * tq);
        }

        float acc[4][4];
#pragma unroll
        for (int nt = 0; nt < 4; nt++)
#pragma unroll
            for (int r = 0; r < 4; r++) acc[nt][r] = 0.f;

        if (t > 0) {
            const __nv_bfloat16* hhi = g_hhi[(t - 1) & 1];
            const __nv_bfloat16* hlo = g_hlo[(t - 1) & 1];

            wait_flags(grp, 0, t, lane);
            stage_warp(hbase_sm, hhi, hlo, w, grp, wm, 0, 0, lane);
            wait_flags(grp, 1, t, lane);
            stage_warp(hbase_sm, hhi, hlo, w, grp, wm, 1, 1, lane);

            for (int kc = 0; kc < 8; kc++) {
                int cur = kc & 1;
                if (kc < 6) asm volatile("cp.async.wait_group 1;");
                else        asm volatile("cp.async.wait_group 0;");

                const __nv_bfloat16* HhC = (const __nv_bfloat16*)
                    ((const unsigned char*)Hbase + ((w * 2 + cur) * 2 + 0) * HBUF_B);
                const __nv_bfloat16* HlC = (const __nv_bfloat16*)
                    ((const unsigned char*)Hbase + ((w * 2 + cur) * 2 + 1) * HBUF_B);
#pragma unroll
                for (int ks = 0; ks < 4; ks++) {
                    int ko = ks * 16 + 2 * tq;
                    int r0 = g, r1 = g + 8;
                    uint32_t ah[4], al[4];
                    ah[0] = *(const uint32_t*)&HhC[r0 * HSTR + ko];
                    ah[1] = *(const uint32_t*)&HhC[r1 * HSTR + ko];
                    ah[2] = *(const uint32_t*)&HhC[r0 * HSTR + ko + 8];
                    ah[3] = *(const uint32_t*)&HhC[r1 * HSTR + ko + 8];
                    al[0] = *(const uint32_t*)&HlC[r0 * HSTR + ko];
                    al[1] = *(const uint32_t*)&HlC[r1 * HSTR + ko];
                    al[2] = *(const uint32_t*)&HlC[r0 * HSTR + ko + 8];
                    al[3] = *(const uint32_t*)&HlC[r1 * HSTR + ko + 8];
                    int kR = grp * 512 + kc * 64 + ks * 16 + 2 * tq;
                    uint32_t bh[4][2], bl[4][2];
#pragma unroll
                    for (int nt = 0; nt < 4; nt++) {
                        int rr = nt * 8 + g;
                        bh[nt][0] = *(const uint32_t*)&Rh[rr * RSTR + kR];
                        bh[nt][1] = *(const uint32_t*)&Rh[rr * RSTR + kR + 8];
                        bl[nt][0] = *(const uint32_t*)&Rl[rr * RSTR + kR];
                        bl[nt][1] = *(const uint32_t*)&Rl[rr * RSTR + kR + 8];
                    }
#pragma unroll
                    for (int nt = 0; nt < 4; nt++) mma16816(acc[nt], ah, bh[nt]);
#pragma unroll
                    for (int nt = 0; nt < 4; nt++) mma16816(acc[nt], ah, bl[nt]);
#pragma unroll
                    for (int nt = 0; nt < 4; nt++) mma16816(acc[nt], al, bh[nt]);
                }
                if (kc + 2 < 8) {
                    wait_flags(grp, kc + 2, t, lane);
                    stage_warp(hbase_sm, hhi, hlo, w, grp, wm, kc + 2, cur, lane);
                }
            }
        }

        // cross-group exchange: ship the jj-half this group does NOT own
        {
            float* slot = Red + ((grp ^ 1) * 128 + wm * 32 + lane) * 9;
            int jbase = (grp == 1) ? 0 : 2;
#pragma unroll
            for (int nt = 0; nt < 4; nt++) {
                slot[nt * 2 + 0] = acc[nt][jbase + 0];
                slot[nt * 2 + 1] = acc[nt][jbase + 1];
            }
        }
        __syncthreads();

        {
            const float* slot = Red + (grp * 128 + wm * 32 + lane) * 9;
            int jbase = grp * 2;
            float* h_out = out_base + (size_t)t * BATCH * HID;
            int cb = t & 1;
#pragma unroll
            for (int cm = 0; cm < 2; cm++) {
                int j = jbase + cm;
                int brow = wm * 16 + g + grp * 8;
                int col  = hc0 + 2 * tq + cm;
                float vi = acc[0][j] + slot[0 * 2 + cm] + (cm ? wxp[0].y : wxp[0].x);
                float vg = acc[1][j] + slot[1 * 2 + cm] + (cm ? wxp[1].y : wxp[1].x);
                float vf = acc[2][j] + slot[2 * 2 + cm] + (cm ? wxp[2].y : wxp[2].x);
                float vo = acc[3][j] + slot[3 * 2 + cm] + (cm ? wxp[3].y : wxp[3].x);
                float ii = sigmoid_fast(vi);
                float gg = tanh_fast(vg);
                float ff = sigmoid_fast(vf);
                float oo = sigmoid_fast(vo);
                float cn = ff * c_reg[cm] + ii * gg;
                c_reg[cm] = cn;
                float h = oo * tanh_fast(cn);
                int idx = brow * HID + col;
                h_out[idx] = h;
                __nv_bfloat16 hi, lo;
                split_bf16(h, hi, lo);
                g_hhi[cb][idx] = hi;
                g_hlo[cb][idx] = lo;
                if (t == T_STEPS - 1) {
                    size_t base = (size_t)T_STEPS * BATCH * HID;
                    out_base[base + idx] = h;
                    out_base[base + BATCH * HID + idx] = cn;
                }
            }
        }

        // publish: all h writes fenced, then bump this CTA's flag to t+1
        __threadfence();
        __syncthreads();
        if (tid == 0)
            asm volatile("st.global.cg.u32 [%0], %1;"
                         :: "l"(&g_arrive[blockIdx.x * 8]), "r"(t + 1));
    }

    // cleanup for graph replay (after ALL CTAs complete); sleep-backoff spins
    if (tid == 0) {
        __threadfence();
        atomicAdd(&g_bar, 1u);
        if (blockIdx.x == 0) {
            while (atomicAdd(&g_bar, 0u) < NCTA) __nanosleep(100);
            for (int i = 0; i < NCTA; i++) g_arrive[i * 8] = 0;
            __threadfence();
            g_bar = 0;
        }
    }
}

extern "C" void kernel_launch(void* const* d_in, const int* in_sizes, int n_in,
                              void* d_out, int out_size)
{
    const float* x    = (const float*)d_in[0];
    const float* Wk   = (const float*)d_in[1];
    const float* Rk   = (const float*)d_in[2];
    const float* bias = (const float*)d_in[3];
    float* out = (float*)d_out;

    cudaFuncSetAttribute(lstm_persistent,
                         cudaFuncAttributeMaxDynamicSharedMemorySize, SMEM_PERS);
    cudaFuncSetAttribute(wx_mma,
                         cudaFuncAttributeMaxDynamicSharedMemorySize, WX_SMEM);

    size_t nx = (size_t)T_STEPS * BATCH * IN_DIM;
    convert_x<<<(unsigned)((nx + 255) / 256), 256>>>(x);
    convert_W<<<dim3(GATES / 32, IN_DIM / 32), dim3(32, 8)>>>(Wk);
    convert_R<<<dim3(GATES / 32, HID / 32), dim3(32, 8)>>>(Rk);

    wx_mma<<<dim3(GATES / 128, (T_STEPS * BATCH) / 128), 256, WX_SMEM>>>(bias);

    lstm_persistent<<<NCTA, 256, SMEM_PERS>>>(out);
}